// round 1
// baseline (speedup 1.0000x reference)
#include <cuda_runtime.h>
#include <math.h>

#define B_ 16
#define L_ 1024
#define H_ 8
#define E_ 64
#define CH 512              // H_*E_
#define NCH 8192            // B_*CH
#define MAXP 524288         // max peaks per batch (>= CH*(L_-2))
#define TPB 256

// ---------------- static scratch (no runtime allocation allowed) ----------------
__device__ float    g_pool_q[B_*(L_/2)*CH];
__device__ float    g_pool_k[B_*(L_/2)*CH];
__device__ float    g_pool_v[B_*(L_/2)*CH];
__device__ float    g_corr[(size_t)NCH*L_];      // [B,H,E,Ls] channel-major
__device__ float    g_cm[B_*L_];
__device__ double   g_sum[B_];
__device__ double   g_sumsq[B_];
__device__ float    g_pk[B_];
__device__ int      g_kvals[B_];
__device__ int      g_krem[B_];
__device__ unsigned g_prefix[B_];
__device__ float    g_thresh[B_];
__device__ int      g_pcount[B_];
__device__ unsigned g_pkeys[(size_t)B_*MAXP];
__device__ unsigned g_hist[B_*256];

__device__ __forceinline__ unsigned f2k(float f) {
    unsigned u = __float_as_uint(f);
    return (u & 0x80000000u) ? ~u : (u | 0x80000000u);
}
__device__ __forceinline__ float k2f(unsigned k) {
    unsigned u = (k & 0x80000000u) ? (k & 0x7fffffffu) : ~k;
    return __uint_as_float(u);
}

// ---------------- pooling (adaptive avg pool, L % s == 0) ----------------
__global__ void pool_kernel(const float* __restrict__ x, float* __restrict__ y, int Ls, int s) {
    int i = blockIdx.x * blockDim.x + threadIdx.x;
    int n = B_ * Ls * CH;
    if (i >= n) return;
    int rem = i % CH;
    int t   = (i / CH) % Ls;
    int b   = i / (CH * Ls);
    const float* p = x + ((size_t)b * L_ + (size_t)t * s) * CH + rem;
    float acc = 0.0f;
    for (int j = 0; j < s; j++) acc += p[(size_t)j * CH];
    y[i] = acc / (float)s;
}

// ---------------- correlation via single packed complex FFT ----------------
// z = q + i*k -> FFT -> S = Q * conj(K) (Hermitian extraction) -> IFFT -> corr (real)
__global__ void corr_fft_kernel(const float* __restrict__ q, const float* __restrict__ k,
                                int Ls, int logN) {
    extern __shared__ float smem[];
    float* sr  = smem;
    float* si  = smem + Ls;
    float* twr = smem + 2 * Ls;
    float* twi = twr + Ls / 2;
    const int N = Ls;
    int ch  = blockIdx.x;
    int b   = ch / CH;
    int rem = ch % CH;
    const size_t base = (size_t)b * Ls * CH + rem;
    int tid = threadIdx.x;

    // load with bit reversal
    for (int t = tid; t < N; t += blockDim.x) {
        int r = __brev((unsigned)t) >> (32 - logN);
        sr[r] = q[base + (size_t)t * CH];
        si[r] = k[base + (size_t)t * CH];
    }
    // twiddle table  w[j] = exp(-2*pi*i*j/N)
    for (int j = tid; j < N / 2; j += blockDim.x) {
        float sv, cv;
        sincosf(-6.2831853071795864f * (float)j / (float)N, &sv, &cv);
        twr[j] = cv; twi[j] = sv;
    }
    __syncthreads();

    // forward DIT stages
    for (int st = 1; st <= logN; st++) {
        int half = 1 << (st - 1);
        for (int j = tid; j < (N >> 1); j += blockDim.x) {
            int grp = j >> (st - 1);
            int pos = j & (half - 1);
            int i0 = (grp << st) + pos;
            int i1 = i0 + half;
            int tj = pos << (logN - st);
            float wr = twr[tj], wi = twi[tj];
            float xr = sr[i1], xi = si[i1];
            float tr = wr * xr - wi * xi;
            float ti = wr * xi + wi * xr;
            float ur = sr[i0], ui = si[i0];
            sr[i0] = ur + tr; si[i0] = ui + ti;
            sr[i1] = ur - tr; si[i1] = ui - ti;
        }
        __syncthreads();
    }

    // spectrum product S[f] = Q[f]*conj(K[f]), mirror S[N-f] = conj(S[f])
    float Srv[3], Siv[3]; int fv[3]; int nf = 0;
    for (int f = tid; f <= N / 2; f += blockDim.x) {
        int g = (N - f) & (N - 1);
        float a = sr[f], bq = si[f];
        float c = sr[g], d  = si[g];
        float qr = 0.5f * (a + c),  qi = 0.5f * (bq - d);
        float kr = 0.5f * (bq + d), ki = 0.5f * (a - c);   // conj(K)
        Srv[nf] = qr * kr - qi * ki;
        Siv[nf] = qr * ki + qi * kr;
        fv[nf]  = f; nf++;
    }
    __syncthreads();
    for (int ii = 0; ii < nf; ii++) {
        int f = fv[ii]; int g = (N - f) & (N - 1);
        sr[f] = Srv[ii]; si[f] =  Siv[ii];
        sr[g] = Srv[ii]; si[g] = -Siv[ii];
    }
    __syncthreads();

    // in-place bit-reverse permutation for second FFT
    for (int t = tid; t < N; t += blockDim.x) {
        int r = __brev((unsigned)t) >> (32 - logN);
        if (r > t) {
            float a = sr[t]; sr[t] = sr[r]; sr[r] = a;
            float bb = si[t]; si[t] = si[r]; si[r] = bb;
        }
    }
    __syncthreads();

    // inverse DIT stages (conjugate twiddles)
    for (int st = 1; st <= logN; st++) {
        int half = 1 << (st - 1);
        for (int j = tid; j < (N >> 1); j += blockDim.x) {
            int grp = j >> (st - 1);
            int pos = j & (half - 1);
            int i0 = (grp << st) + pos;
            int i1 = i0 + half;
            int tj = pos << (logN - st);
            float wr = twr[tj], wi = -twi[tj];
            float xr = sr[i1], xi = si[i1];
            float tr = wr * xr - wi * xi;
            float ti = wr * xi + wi * xr;
            float ur = sr[i0], ui = si[i0];
            sr[i0] = ur + tr; si[i0] = ui + ti;
            sr[i1] = ur - tr; si[i1] = ui - ti;
        }
        __syncthreads();
    }

    float invN = 1.0f / (float)N;
    float* out = g_corr + (size_t)ch * Ls;
    for (int t = tid; t < N; t += blockDim.x) out[t] = sr[t] * invN;
}

// ---------------- batch statistics ----------------
__global__ void stats_kernel(int Ls) {
    __shared__ double rs[TPB];
    __shared__ double rq[TPB];
    int ch = blockIdx.x; int b = ch / CH; int tid = threadIdx.x;
    const float* c = g_corr + (size_t)ch * Ls;
    double s = 0.0, qq = 0.0;
    for (int t = tid; t < Ls; t += blockDim.x) { double v = (double)c[t]; s += v; qq += v * v; }
    rs[tid] = s; rq[tid] = qq;
    __syncthreads();
    for (int o = TPB / 2; o > 0; o >>= 1) {
        if (tid < o) { rs[tid] += rs[tid + o]; rq[tid] += rq[tid + o]; }
        __syncthreads();
    }
    if (tid == 0) { atomicAdd(&g_sum[b], rs[0]); atomicAdd(&g_sumsq[b], rq[0]); }
}

__global__ void cm_kernel(int Ls) {
    int i = blockIdx.x * blockDim.x + threadIdx.x;
    if (i >= B_ * Ls) return;
    int b = i / Ls; int t = i % Ls;
    const float* base = g_corr + (size_t)b * CH * Ls + t;
    float acc = 0.0f;
    for (int ch = 0; ch < CH; ch++) acc += base[(size_t)ch * Ls];
    g_cm[b * Ls + t] = acc * (1.0f / (float)CH);
}

__global__ void pk_kernel(int Ls) {
    __shared__ int red[TPB];
    int b = blockIdx.x; int tid = threadIdx.x;
    const float* cm = g_cm + (size_t)b * Ls;
    int cnt = 0;
    for (int t = tid + 1; t < Ls - 1; t += blockDim.x) {
        float v = cm[t];
        if (v > cm[t - 1] && v > cm[t + 1]) cnt++;
    }
    red[tid] = cnt;
    __syncthreads();
    for (int o = TPB / 2; o > 0; o >>= 1) {
        if (tid < o) red[tid] += red[tid + o];
        __syncthreads();
    }
    if (tid == 0) g_pk[b] = (float)red[0];
}

// ---------------- tiny MLP: feats -> k ----------------
__global__ void mlp_kernel(const float* __restrict__ w1, const float* __restrict__ b1,
                           const float* __restrict__ w2, const float* __restrict__ b2,
                           const float* __restrict__ w3, const float* __restrict__ b3,
                           int Ls) {
    int b = threadIdx.x;
    if (b >= B_) return;
    double tot = 0.0;
    for (int i = 0; i < B_; i++) tot += g_sumsq[i];
    float energy = (float)(tot / ((double)B_ * (double)Ls));
    double n = (double)CH * (double)Ls;
    double s1 = g_sum[b], s2 = g_sumsq[b];
    double mean = s1 / n;
    float var = (float)((s2 - mean * s1) / (n - 1.0));
    float f0 = energy, f1 = var, f2 = g_pk[b];
    float h1[32];
    for (int j = 0; j < 32; j++) {
        float a = w1[j * 3] * f0 + w1[j * 3 + 1] * f1 + w1[j * 3 + 2] * f2 + b1[j];
        h1[j] = a > 0.0f ? a : 0.0f;
    }
    float h2[16];
    for (int j = 0; j < 16; j++) {
        float a = b2[j];
        for (int i2 = 0; i2 < 32; i2++) a += w2[j * 32 + i2] * h1[i2];
        h2[j] = a > 0.0f ? a : 0.0f;
    }
    float a = b3[0];
    for (int i2 = 0; i2 < 16; i2++) a += w3[i2] * h2[i2];
    float ratio = 1.0f / (1.0f + expf(-a));
    int kv = (int)(ratio * (float)Ls);
    if (kv < 1) kv = 1;
    if (kv > Ls) kv = Ls;
    g_kvals[b] = kv;
    g_krem[b]  = kv;
    g_prefix[b] = 0u;
}

// ---------------- peak compaction ----------------
__global__ void peaks_kernel(int Ls) {
    extern __shared__ float sc[];
    __shared__ int s_cnt, s_base;
    int ch = blockIdx.x; int b = ch / CH; int tid = threadIdx.x;
    const float* c = g_corr + (size_t)ch * Ls;
    for (int t = tid; t < Ls; t += blockDim.x) sc[t] = c[t];
    if (tid == 0) s_cnt = 0;
    __syncthreads();
    int loc = 0;
    for (int t = tid + 1; t < Ls - 1; t += blockDim.x) {
        float v = sc[t];
        if (v > sc[t - 1] && v > sc[t + 1]) loc++;
    }
    atomicAdd(&s_cnt, loc);
    __syncthreads();
    if (tid == 0) { s_base = atomicAdd(&g_pcount[b], s_cnt); s_cnt = 0; }
    __syncthreads();
    unsigned* keys = g_pkeys + (size_t)b * MAXP;
    for (int t = tid + 1; t < Ls - 1; t += blockDim.x) {
        float v = sc[t];
        if (v > sc[t - 1] && v > sc[t + 1]) {
            int pos = atomicAdd(&s_cnt, 1);
            keys[s_base + pos] = f2k(v);
        }
    }
}

// ---------------- radix select (k-th largest) ----------------
__global__ void select_hist_kernel(int sh, int first) {
    __shared__ unsigned hl[256];
    int b = blockIdx.y;
    for (int i = threadIdx.x; i < 256; i += blockDim.x) hl[i] = 0;
    __syncthreads();
    int cnt = g_pcount[b];
    unsigned ph = first ? 0u : (g_prefix[b] >> (sh + 8));
    const unsigned* keys = g_pkeys + (size_t)b * MAXP;
    for (int i = blockIdx.x * blockDim.x + threadIdx.x; i < cnt; i += gridDim.x * blockDim.x) {
        unsigned key = keys[i];
        if (first || (key >> (sh + 8)) == ph)
            atomicAdd(&hl[(key >> sh) & 255u], 1u);
    }
    __syncthreads();
    for (int i = threadIdx.x; i < 256; i += blockDim.x)
        if (hl[i]) atomicAdd(&g_hist[b * 256 + i], hl[i]);
}

__global__ void select_scan_kernel(int sh, int last) {
    int b = threadIdx.x;
    if (b >= B_) return;
    unsigned k = (unsigned)g_krem[b];
    unsigned cum = 0; unsigned chosen = 0;
    for (int bin = 255; bin >= 0; --bin) {
        unsigned h = g_hist[b * 256 + bin];
        if (cum + h >= k) { chosen = (unsigned)bin; g_krem[b] = (int)(k - cum); break; }
        cum += h;
    }
    g_prefix[b] |= chosen << sh;
    if (last) g_thresh[b] = k2f(g_prefix[b]);
}

// ---------------- masked softmax * v, interpolation, accumulation ----------------
__global__ void final_kernel(const float* __restrict__ vv, const float* __restrict__ swarr,
                             int swi, int Ls, int s, float* __restrict__ out) {
    extern __shared__ float smem[];
    float* sc = smem;        // corr row
    float* so = smem + Ls;   // attn -> w*v
    __shared__ float red[TPB];
    int ch = blockIdx.x; int b = ch / CH; int rem = ch % CH;
    int tid = threadIdx.x;
    const float* c = g_corr + (size_t)ch * Ls;
    for (int t = tid; t < Ls; t += blockDim.x) sc[t] = c[t];
    __syncthreads();

    float thr = g_thresh[b];
    bool useAll = (g_pcount[b] <= g_kvals[b]);

    float m = 0.0f;   // zeros always present in attn
    for (int t = tid; t < Ls; t += blockDim.x) {
        float a = 0.0f;
        if (t > 0 && t < Ls - 1) {
            float v = sc[t];
            if (v > sc[t - 1] && v > sc[t + 1] && (useAll || v >= thr)) a = v;
        }
        so[t] = a;
        m = fmaxf(m, a);
    }
    red[tid] = m; __syncthreads();
    for (int o = TPB / 2; o > 0; o >>= 1) {
        if (tid < o) red[tid] = fmaxf(red[tid], red[tid + o]);
        __syncthreads();
    }
    m = red[0]; __syncthreads();

    float ds = 0.0f;
    for (int t = tid; t < Ls; t += blockDim.x) ds += expf(so[t] - m);
    red[tid] = ds; __syncthreads();
    for (int o = TPB / 2; o > 0; o >>= 1) {
        if (tid < o) red[tid] += red[tid + o];
        __syncthreads();
    }
    float inv = 1.0f / red[0]; __syncthreads();

    const size_t vbase = (size_t)b * Ls * CH + rem;
    for (int t = tid; t < Ls; t += blockDim.x)
        so[t] = expf(so[t] - m) * inv * vv[vbase + (size_t)t * CH];
    __syncthreads();

    float sw = swarr[swi];
    const size_t obase = (size_t)b * L_ * CH + rem;
    if (s == 1) {
        for (int t = tid; t < L_; t += blockDim.x)
            out[obase + (size_t)t * CH] = sw * so[t];
    } else {
        float invs = 1.0f / (float)s;
        for (int t = tid; t < L_; t += blockDim.x) {
            float src = ((float)t + 0.5f) * invs - 0.5f;
            if (src < 0.0f) src = 0.0f;
            int x0 = (int)src;
            int x1 = x0 + 1; if (x1 > Ls - 1) x1 = Ls - 1;
            float lam = src - (float)x0;
            float val = so[x0] * (1.0f - lam) + so[x1] * lam;
            out[obase + (size_t)t * CH] += sw * val;
        }
    }
}

// ---------------- launch ----------------
extern "C" void kernel_launch(void* const* d_in, const int* in_sizes, int n_in,
                              void* d_out, int out_size) {
    (void)in_sizes; (void)n_in; (void)out_size;
    const float* q  = (const float*)d_in[0];
    const float* kk = (const float*)d_in[1];
    const float* v  = (const float*)d_in[2];
    const float* sw = (const float*)d_in[3];
    const float* w1 = (const float*)d_in[4];
    const float* b1 = (const float*)d_in[5];
    const float* w2 = (const float*)d_in[6];
    const float* b2 = (const float*)d_in[7];
    const float* w3 = (const float*)d_in[8];
    const float* b3 = (const float*)d_in[9];
    float* out = (float*)d_out;

    void *p_sum = 0, *p_sumsq = 0, *p_pcount = 0, *p_hist = 0;
    void *p_pq = 0, *p_pkk = 0, *p_pv = 0;
    cudaGetSymbolAddress(&p_sum, g_sum);
    cudaGetSymbolAddress(&p_sumsq, g_sumsq);
    cudaGetSymbolAddress(&p_pcount, g_pcount);
    cudaGetSymbolAddress(&p_hist, g_hist);
    cudaGetSymbolAddress(&p_pq, g_pool_q);
    cudaGetSymbolAddress(&p_pkk, g_pool_k);
    cudaGetSymbolAddress(&p_pv, g_pool_v);
    float* poolq = (float*)p_pq;
    float* poolk = (float*)p_pkk;
    float* poolv = (float*)p_pv;

    const int scales[3] = {1, 2, 4};
    for (int si = 0; si < 3; si++) {
        int s = scales[si];
        int Ls = L_ / s;
        int logN = (s == 1) ? 10 : ((s == 2) ? 9 : 8);
        const float *qs = q, *ks = kk, *vs = v;
        if (s > 1) {
            int n = B_ * Ls * CH;
            int gb = (n + TPB - 1) / TPB;
            pool_kernel<<<gb, TPB>>>(q,  poolq, Ls, s);
            pool_kernel<<<gb, TPB>>>(kk, poolk, Ls, s);
            pool_kernel<<<gb, TPB>>>(v,  poolv, Ls, s);
            qs = poolq; ks = poolk; vs = poolv;
        }
        corr_fft_kernel<<<NCH, TPB, 3 * Ls * sizeof(float)>>>(qs, ks, Ls, logN);

        cudaMemsetAsync(p_sum,    0, B_ * sizeof(double));
        cudaMemsetAsync(p_sumsq,  0, B_ * sizeof(double));
        cudaMemsetAsync(p_pcount, 0, B_ * sizeof(int));

        stats_kernel<<<NCH, TPB>>>(Ls);
        cm_kernel<<<(B_ * Ls + TPB - 1) / TPB, TPB>>>(Ls);
        pk_kernel<<<B_, TPB>>>(Ls);
        mlp_kernel<<<1, 32>>>(w1, b1, w2, b2, w3, b3, Ls);
        peaks_kernel<<<NCH, TPB, Ls * sizeof(float)>>>(Ls);

        for (int p = 0; p < 4; p++) {
            cudaMemsetAsync(p_hist, 0, B_ * 256 * sizeof(unsigned));
            dim3 hg(64, B_);
            select_hist_kernel<<<hg, TPB>>>(24 - 8 * p, p == 0 ? 1 : 0);
            select_scan_kernel<<<1, 32>>>(24 - 8 * p, p == 3 ? 1 : 0);
        }

        final_kernel<<<NCH, TPB, 2 * Ls * sizeof(float)>>>(vs, sw, si, Ls, s, out);
    }
}

// round 2
// speedup vs baseline: 1.7827x; 1.7827x over previous
#include <cuda_runtime.h>
#include <math.h>

#define B_ 16
#define L_ 1024
#define H_ 8
#define E_ 64
#define CH 512              // H_*E_
#define NCH 8192            // B_*CH
#define MAXP 524288         // max peaks per batch (>= CH*(L_-2))
#define TPB 256

// ---------------- static scratch (no runtime allocation allowed) ----------------
__device__ float    g_qT[(size_t)B_*CH*L_];
__device__ float    g_kT[(size_t)B_*CH*L_];
__device__ float    g_vT[(size_t)B_*CH*L_];
__device__ float    g_pq[(size_t)B_*CH*(L_/2)];
__device__ float    g_pk2[(size_t)B_*CH*(L_/2)];
__device__ float    g_pv[(size_t)B_*CH*(L_/2)];
__device__ float    g_corr[(size_t)NCH*L_];      // [B*CH, Ls] row-major (channel-major)
__device__ float    g_outT[(size_t)B_*CH*L_];    // accumulated output, channel-major
__device__ float    g_cm[B_*L_];
__device__ double   g_sum[B_];
__device__ double   g_sumsq[B_];
__device__ int      g_kvals[B_];
__device__ int      g_krem[B_];
__device__ unsigned g_prefix[B_];
__device__ float    g_thresh[B_];
__device__ int      g_pcount[B_];
__device__ unsigned g_pkeys[(size_t)B_*MAXP];
__device__ unsigned g_hist[B_*256];

__device__ __forceinline__ unsigned f2k(float f) {
    unsigned u = __float_as_uint(f);
    return (u & 0x80000000u) ? ~u : (u | 0x80000000u);
}
__device__ __forceinline__ float k2f(unsigned k) {
    unsigned u = (k & 0x80000000u) ? (k & 0x7fffffffu) : ~k;
    return __uint_as_float(u);
}

// ---------------- transpose [B,L,CH] -> [B,CH,L] for q,k,v ----------------
__global__ void transpose3_kernel(const float* __restrict__ q,
                                  const float* __restrict__ k,
                                  const float* __restrict__ v) {
    __shared__ float tile[32][33];
    int b   = blockIdx.z;
    int ch0 = blockIdx.x * 32;
    int l0  = blockIdx.y * 32;
    const float* ins[3] = {q, k, v};
    float* outs[3] = {g_qT, g_kT, g_vT};
    int tx = threadIdx.x, ty = threadIdx.y;
    #pragma unroll
    for (int m = 0; m < 3; m++) {
        const float* in = ins[m];
        float* out = outs[m];
        for (int r = ty; r < 32; r += 8)
            tile[r][tx] = in[((size_t)b * L_ + (l0 + r)) * CH + ch0 + tx];
        __syncthreads();
        for (int r = ty; r < 32; r += 8)
            out[((size_t)b * CH + (ch0 + r)) * L_ + l0 + tx] = tile[tx][r];
        __syncthreads();
    }
}

// ---------------- untranspose [B,CH,L] -> [B,L,CH] ----------------
__global__ void untranspose_kernel(float* __restrict__ out) {
    __shared__ float tile[32][33];
    int b   = blockIdx.z;
    int ch0 = blockIdx.x * 32;
    int l0  = blockIdx.y * 32;
    int tx = threadIdx.x, ty = threadIdx.y;
    for (int r = ty; r < 32; r += 8)
        tile[r][tx] = g_outT[((size_t)b * CH + (ch0 + r)) * L_ + l0 + tx];
    __syncthreads();
    for (int r = ty; r < 32; r += 8)
        out[((size_t)b * L_ + (l0 + r)) * CH + ch0 + tx] = tile[tx][r];
}

// ---------------- per-scale init ----------------
__global__ void init_kernel(int Ls) {
    int i = blockIdx.x * blockDim.x + threadIdx.x;
    int stride = gridDim.x * blockDim.x;
    for (int j = i; j < B_ * Ls; j += stride) g_cm[j] = 0.0f;
    for (int j = i; j < B_ * 256; j += stride) g_hist[j] = 0u;
    if (i < B_) {
        g_sum[i] = 0.0; g_sumsq[i] = 0.0; g_pcount[i] = 0;
    }
}

// ---------------- pooling in transposed layout (vectorized) ----------------
__global__ void pool_kernel(int Ls, int s) {
    int i = blockIdx.x * blockDim.x + threadIdx.x;
    if (i >= B_ * CH * Ls) return;
    size_t src = (size_t)(i / Ls) * L_ + (size_t)(i % Ls) * s;
    if (s == 2) {
        float2 a = *(const float2*)(g_qT + src); g_pq[i]  = (a.x + a.y) * 0.5f;
        float2 b = *(const float2*)(g_kT + src); g_pk2[i] = (b.x + b.y) * 0.5f;
        float2 c = *(const float2*)(g_vT + src); g_pv[i]  = (c.x + c.y) * 0.5f;
    } else {
        float4 a = *(const float4*)(g_qT + src); g_pq[i]  = (a.x + a.y + a.z + a.w) * 0.25f;
        float4 b = *(const float4*)(g_kT + src); g_pk2[i] = (b.x + b.y + b.z + b.w) * 0.25f;
        float4 c = *(const float4*)(g_vT + src); g_pv[i]  = (c.x + c.y + c.z + c.w) * 0.25f;
    }
}

// ---------------- correlation via single packed complex FFT + fused epilogue ----------------
// z = q + i*k -> FFT -> S = Q*conj(K) (Hermitian extraction) -> IFFT -> corr
// epilogue: write corr row, per-batch sum/sumsq atomics, peak compaction.
__global__ void corr_fft_kernel(const float* __restrict__ q, const float* __restrict__ k,
                                int Ls, int logN) {
    extern __shared__ float smem[];
    float* sr  = smem;
    float* si  = smem + Ls;
    float* twr = smem + 2 * Ls;
    float* twi = twr + Ls / 2;
    __shared__ double rs[TPB];
    __shared__ double rq[TPB];
    __shared__ int s_cnt, s_base;
    const int N = Ls;
    int ch  = blockIdx.x;
    int b   = ch / CH;
    const size_t base = (size_t)ch * Ls;
    int tid = threadIdx.x;

    // coalesced load with bit-reversal scatter into smem
    for (int t = tid; t < N; t += blockDim.x) {
        int r = __brev((unsigned)t) >> (32 - logN);
        sr[r] = q[base + t];
        si[r] = k[base + t];
    }
    for (int j = tid; j < N / 2; j += blockDim.x) {
        float sv, cv;
        sincosf(-6.2831853071795864f * (float)j / (float)N, &sv, &cv);
        twr[j] = cv; twi[j] = sv;
    }
    __syncthreads();

    // forward DIT
    for (int st = 1; st <= logN; st++) {
        int half = 1 << (st - 1);
        for (int j = tid; j < (N >> 1); j += blockDim.x) {
            int grp = j >> (st - 1);
            int pos = j & (half - 1);
            int i0 = (grp << st) + pos;
            int i1 = i0 + half;
            int tj = pos << (logN - st);
            float wr = twr[tj], wi = twi[tj];
            float xr = sr[i1], xi = si[i1];
            float tr = wr * xr - wi * xi;
            float ti = wr * xi + wi * xr;
            float ur = sr[i0], ui = si[i0];
            sr[i0] = ur + tr; si[i0] = ui + ti;
            sr[i1] = ur - tr; si[i1] = ui - ti;
        }
        __syncthreads();
    }

    // S[f] = Q[f]*conj(K[f]); mirror S[N-f] = conj(S[f])
    float Srv[3], Siv[3]; int fv[3]; int nf = 0;
    for (int f = tid; f <= N / 2; f += blockDim.x) {
        int g = (N - f) & (N - 1);
        float a = sr[f], bq = si[f];
        float c = sr[g], d  = si[g];
        float qr = 0.5f * (a + c),  qi = 0.5f * (bq - d);
        float kr = 0.5f * (bq + d), ki = 0.5f * (a - c);
        Srv[nf] = qr * kr - qi * ki;
        Siv[nf] = qr * ki + qi * kr;
        fv[nf]  = f; nf++;
    }
    __syncthreads();
    for (int ii = 0; ii < nf; ii++) {
        int f = fv[ii]; int g = (N - f) & (N - 1);
        sr[f] = Srv[ii]; si[f] =  Siv[ii];
        sr[g] = Srv[ii]; si[g] = -Siv[ii];
    }
    __syncthreads();

    // bit-reverse permute
    for (int t = tid; t < N; t += blockDim.x) {
        int r = __brev((unsigned)t) >> (32 - logN);
        if (r > t) {
            float a = sr[t]; sr[t] = sr[r]; sr[r] = a;
            float bb = si[t]; si[t] = si[r]; si[r] = bb;
        }
    }
    __syncthreads();

    // inverse DIT (conjugate twiddles)
    for (int st = 1; st <= logN; st++) {
        int half = 1 << (st - 1);
        for (int j = tid; j < (N >> 1); j += blockDim.x) {
            int grp = j >> (st - 1);
            int pos = j & (half - 1);
            int i0 = (grp << st) + pos;
            int i1 = i0 + half;
            int tj = pos << (logN - st);
            float wr = twr[tj], wi = -twi[tj];
            float xr = sr[i1], xi = si[i1];
            float tr = wr * xr - wi * xi;
            float ti = wr * xi + wi * xr;
            float ur = sr[i0], ui = si[i0];
            sr[i0] = ur + tr; si[i0] = ui + ti;
            sr[i1] = ur - tr; si[i1] = ui - ti;
        }
        __syncthreads();
    }

    // ---- fused epilogue ----
    const float invN = 1.0f / (float)N;   // exact power of two
    float* out = g_corr + base;
    double s = 0.0, ss = 0.0;
    for (int t = tid; t < N; t += blockDim.x) {
        float val = sr[t] * invN;
        out[t] = val;
        s += (double)val;
        ss += (double)val * (double)val;
    }
    rs[tid] = s; rq[tid] = ss;
    if (tid == 0) s_cnt = 0;
    __syncthreads();
    for (int o = TPB / 2; o > 0; o >>= 1) {
        if (tid < o) { rs[tid] += rs[tid + o]; rq[tid] += rq[tid + o]; }
        __syncthreads();
    }
    if (tid == 0) {
        atomicAdd(&g_sum[b], rs[0]);
        atomicAdd(&g_sumsq[b], rq[0]);
    }

    // peak count (comparisons invariant to exact 2^-k scaling)
    int loc = 0;
    for (int t = tid + 1; t < N - 1; t += blockDim.x) {
        float v = sr[t];
        if (v > sr[t - 1] && v > sr[t + 1]) loc++;
    }
    if (loc) atomicAdd(&s_cnt, loc);
    __syncthreads();
    if (tid == 0) { s_base = atomicAdd(&g_pcount[b], s_cnt); s_cnt = 0; }
    __syncthreads();
    unsigned* keys = g_pkeys + (size_t)b * MAXP;
    for (int t = tid + 1; t < N - 1; t += blockDim.x) {
        float v = sr[t];
        if (v > sr[t - 1] && v > sr[t + 1]) {
            int pos = atomicAdd(&s_cnt, 1);
            keys[s_base + pos] = f2k(v * invN);
        }
    }
}

// ---------------- cm: mean over channels ----------------
__global__ void cm_kernel(int Ls) {
    int i = blockIdx.x * blockDim.x + threadIdx.x;
    if (i >= B_ * Ls) return;
    int b = i / Ls; int t = i % Ls;
    const float* base = g_corr + (size_t)b * CH * Ls + t;
    float a0 = 0.f, a1 = 0.f, a2 = 0.f, a3 = 0.f;
    #pragma unroll 4
    for (int ch = 0; ch < CH; ch += 4) {
        a0 += base[(size_t)ch * Ls];
        a1 += base[(size_t)(ch + 1) * Ls];
        a2 += base[(size_t)(ch + 2) * Ls];
        a3 += base[(size_t)(ch + 3) * Ls];
    }
    g_cm[b * Ls + t] = (a0 + a1 + a2 + a3) * (1.0f / (float)CH);
}

// ---------------- pk over cm + tiny MLP -> kvals (one block per batch) ----------------
__global__ void pkmlp_kernel(const float* __restrict__ w1, const float* __restrict__ b1,
                             const float* __restrict__ w2, const float* __restrict__ b2,
                             const float* __restrict__ w3, const float* __restrict__ b3,
                             int Ls) {
    __shared__ int red[TPB];
    int b = blockIdx.x; int tid = threadIdx.x;
    const float* cm = g_cm + (size_t)b * Ls;
    int cnt = 0;
    for (int t = tid + 1; t < Ls - 1; t += blockDim.x) {
        float v = cm[t];
        if (v > cm[t - 1] && v > cm[t + 1]) cnt++;
    }
    red[tid] = cnt;
    __syncthreads();
    for (int o = TPB / 2; o > 0; o >>= 1) {
        if (tid < o) red[tid] += red[tid + o];
        __syncthreads();
    }
    if (tid == 0) {
        float f2 = (float)red[0];
        double tot = 0.0;
        for (int i = 0; i < B_; i++) tot += g_sumsq[i];
        float f0 = (float)(tot / ((double)B_ * (double)Ls));        // energy
        double n = (double)CH * (double)Ls;
        double s1 = g_sum[b], s2 = g_sumsq[b];
        double mean = s1 / n;
        float f1 = (float)((s2 - mean * s1) / (n - 1.0));           // unbiased var
        float h1[32];
        for (int j = 0; j < 32; j++) {
            float a = w1[j * 3] * f0 + w1[j * 3 + 1] * f1 + w1[j * 3 + 2] * f2 + b1[j];
            h1[j] = a > 0.0f ? a : 0.0f;
        }
        float h2[16];
        for (int j = 0; j < 16; j++) {
            float a = b2[j];
            for (int i2 = 0; i2 < 32; i2++) a += w2[j * 32 + i2] * h1[i2];
            h2[j] = a > 0.0f ? a : 0.0f;
        }
        float a = b3[0];
        for (int i2 = 0; i2 < 16; i2++) a += w3[i2] * h2[i2];
        float ratio = 1.0f / (1.0f + expf(-a));
        int kv = (int)(ratio * (float)Ls);
        if (kv < 1) kv = 1;
        if (kv > Ls) kv = Ls;
        g_kvals[b] = kv;
        g_krem[b]  = kv;
        g_prefix[b] = 0u;
    }
}

// ---------------- radix select (k-th largest) ----------------
__global__ void select_hist_kernel(int sh, int first) {
    __shared__ unsigned hl[256];
    int b = blockIdx.y;
    for (int i = threadIdx.x; i < 256; i += blockDim.x) hl[i] = 0;
    __syncthreads();
    int cnt = g_pcount[b];
    unsigned ph = first ? 0u : (g_prefix[b] >> (sh + 8));
    const unsigned* keys = g_pkeys + (size_t)b * MAXP;
    for (int i = blockIdx.x * blockDim.x + threadIdx.x; i < cnt; i += gridDim.x * blockDim.x) {
        unsigned key = keys[i];
        if (first || (key >> (sh + 8)) == ph)
            atomicAdd(&hl[(key >> sh) & 255u], 1u);
    }
    __syncthreads();
    for (int i = threadIdx.x; i < 256; i += blockDim.x)
        if (hl[i]) atomicAdd(&g_hist[b * 256 + i], hl[i]);
}

__global__ void select_scan_kernel(int sh, int last) {
    int tid = threadIdx.x;
    if (tid < B_) {
        int b = tid;
        unsigned k = (unsigned)g_krem[b];
        unsigned cum = 0; unsigned chosen = 0;
        for (int bin = 255; bin >= 0; --bin) {
            unsigned h = g_hist[b * 256 + bin];
            if (cum + h >= k) { chosen = (unsigned)bin; g_krem[b] = (int)(k - cum); break; }
            cum += h;
        }
        g_prefix[b] |= chosen << sh;
        if (last) g_thresh[b] = k2f(g_prefix[b]);
    }
    __syncthreads();
    // zero hist for next pass / next scale
    for (int i = tid; i < B_ * 256; i += blockDim.x) g_hist[i] = 0u;
}

// ---------------- masked softmax * v, interpolation, accumulation (channel-major) ----------------
__global__ void final_kernel(const float* __restrict__ vv, const float* __restrict__ swarr,
                             int swi, int Ls, int s) {
    extern __shared__ float smem[];
    float* sc = smem;        // corr row
    float* so = smem + Ls;   // attn -> w*v
    __shared__ float red[TPB];
    int ch = blockIdx.x; int b = ch / CH;
    int tid = threadIdx.x;
    const float* c = g_corr + (size_t)ch * Ls;
    for (int t = tid; t < Ls; t += blockDim.x) sc[t] = c[t];
    __syncthreads();

    float thr = g_thresh[b];
    bool useAll = (g_pcount[b] <= g_kvals[b]);

    float m = 0.0f;   // zeros always present in attn
    for (int t = tid; t < Ls; t += blockDim.x) {
        float a = 0.0f;
        if (t > 0 && t < Ls - 1) {
            float v = sc[t];
            if (v > sc[t - 1] && v > sc[t + 1] && (useAll || v >= thr)) a = v;
        }
        so[t] = a;
        m = fmaxf(m, a);
    }
    red[tid] = m; __syncthreads();
    for (int o = TPB / 2; o > 0; o >>= 1) {
        if (tid < o) red[tid] = fmaxf(red[tid], red[tid + o]);
        __syncthreads();
    }
    m = red[0]; __syncthreads();

    float ds = 0.0f;
    for (int t = tid; t < Ls; t += blockDim.x) ds += expf(so[t] - m);
    red[tid] = ds; __syncthreads();
    for (int o = TPB / 2; o > 0; o >>= 1) {
        if (tid < o) red[tid] += red[tid + o];
        __syncthreads();
    }
    float inv = 1.0f / red[0]; __syncthreads();

    const size_t vbase = (size_t)ch * Ls;
    for (int t = tid; t < Ls; t += blockDim.x)
        so[t] = expf(so[t] - m) * inv * vv[vbase + t];
    __syncthreads();

    float sw = swarr[swi];
    float* outRow = g_outT + (size_t)ch * L_;
    if (s == 1) {
        for (int t = tid; t < L_; t += blockDim.x)
            outRow[t] = sw * so[t];
    } else {
        float invs = 1.0f / (float)s;
        for (int t = tid; t < L_; t += blockDim.x) {
            float src = ((float)t + 0.5f) * invs - 0.5f;
            if (src < 0.0f) src = 0.0f;
            int x0 = (int)src;
            int x1 = x0 + 1; if (x1 > Ls - 1) x1 = Ls - 1;
            float lam = src - (float)x0;
            float val = so[x0] * (1.0f - lam) + so[x1] * lam;
            outRow[t] += sw * val;
        }
    }
}

// ---------------- launch ----------------
extern "C" void kernel_launch(void* const* d_in, const int* in_sizes, int n_in,
                              void* d_out, int out_size) {
    (void)in_sizes; (void)n_in; (void)out_size;
    const float* q  = (const float*)d_in[0];
    const float* kk = (const float*)d_in[1];
    const float* v  = (const float*)d_in[2];
    const float* sw = (const float*)d_in[3];
    const float* w1 = (const float*)d_in[4];
    const float* b1 = (const float*)d_in[5];
    const float* w2 = (const float*)d_in[6];
    const float* b2 = (const float*)d_in[7];
    const float* w3 = (const float*)d_in[8];
    const float* b3 = (const float*)d_in[9];
    float* out = (float*)d_out;

    void *p_qT = 0, *p_kT = 0, *p_vT = 0, *p_pq = 0, *p_pk = 0, *p_pv = 0;
    cudaGetSymbolAddress(&p_qT, g_qT);
    cudaGetSymbolAddress(&p_kT, g_kT);
    cudaGetSymbolAddress(&p_vT, g_vT);
    cudaGetSymbolAddress(&p_pq, g_pq);
    cudaGetSymbolAddress(&p_pk, g_pk2);
    cudaGetSymbolAddress(&p_pv, g_pv);

    dim3 tgrid(CH / 32, L_ / 32, B_);
    dim3 tblk(32, 8);
    transpose3_kernel<<<tgrid, tblk>>>(q, kk, v);

    const int scales[3] = {1, 2, 4};
    for (int si = 0; si < 3; si++) {
        int s = scales[si];
        int Ls = L_ / s;
        int logN = (s == 1) ? 10 : ((s == 2) ? 9 : 8);

        init_kernel<<<64, TPB>>>(Ls);

        const float *qs, *ks, *vs;
        if (s > 1) {
            int n = B_ * CH * Ls;
            pool_kernel<<<(n + TPB - 1) / TPB, TPB>>>(Ls, s);
            qs = (const float*)p_pq; ks = (const float*)p_pk; vs = (const float*)p_pv;
        } else {
            qs = (const float*)p_qT; ks = (const float*)p_kT; vs = (const float*)p_vT;
        }

        corr_fft_kernel<<<NCH, TPB, 3 * Ls * sizeof(float)>>>(qs, ks, Ls, logN);
        cm_kernel<<<(B_ * Ls + TPB - 1) / TPB, TPB>>>(Ls);
        pkmlp_kernel<<<B_, TPB>>>(w1, b1, w2, b2, w3, b3, Ls);

        for (int p = 0; p < 4; p++) {
            dim3 hg(64, B_);
            select_hist_kernel<<<hg, TPB>>>(24 - 8 * p, p == 0 ? 1 : 0);
            select_scan_kernel<<<1, TPB>>>(24 - 8 * p, p == 3 ? 1 : 0);
        }

        final_kernel<<<NCH, TPB, 2 * Ls * sizeof(float)>>>(vs, sw, si, Ls, s);
    }

    untranspose_kernel<<<tgrid, tblk>>>(out);
}

// round 4
// speedup vs baseline: 2.3595x; 1.3236x over previous
#include <cuda_runtime.h>
#include <math.h>

#define B_ 16
#define L_ 1024
#define CH 512
#define NCH 8192        // B_*CH
#define TPB 256
#define NSEG 48         // 3 scales * 16 batches
#define TOTL 1792       // 1024+512+256

// ---------------- static scratch ----------------
__device__ float     g_qT[(size_t)NCH*L_];
__device__ float     g_kT[(size_t)NCH*L_];
__device__ float     g_vT[(size_t)NCH*L_];
__device__ float     g_corr[(size_t)NCH*TOTL];
__device__ float     g_out3[(size_t)3*NCH*L_];
__device__ unsigned  g_pkeys[(size_t)NCH*TOTL];
__device__ float2    g_twid[896];
__device__ long long g_cmll[B_*TOTL];
__device__ long long g_sumll[NSEG];
__device__ long long g_sqll[NSEG];
__device__ int       g_kvals[NSEG];
__device__ int       g_krem[NSEG];
__device__ unsigned  g_prefix[NSEG];
__device__ float     g_thresh[NSEG];
__device__ int       g_pcount[NSEG];
__device__ unsigned  g_hist[NSEG*256];

__constant__ int    cLs[3]    = {1024, 512, 256};
__constant__ int    cLogN[3]  = {10, 9, 8};
__constant__ int    cTwOff[3] = {0, 512, 768};
__constant__ int    cCmSeg[3] = {0, 16384, 24576};

#define SCCM 68719476736.0f   // 2^36 fixed-point scale for cm (per-element, max ~7e15)
#define SCST 268435456.0      // 2^28 fixed-point scale for batch stats (max ~1.4e17, NO overflow)

__device__ __forceinline__ size_t corrOff(int s) {
    return s == 0 ? 0 : (s == 1 ? (size_t)NCH*1024 : (size_t)NCH*1536);
}
__device__ __forceinline__ unsigned f2k(float f) {
    unsigned u = __float_as_uint(f);
    return (u & 0x80000000u) ? ~u : (u | 0x80000000u);
}
__device__ __forceinline__ float k2f(unsigned k) {
    unsigned u = (k & 0x80000000u) ? (k & 0x7fffffffu) : ~k;
    return __uint_as_float(u);
}

// ---------------- init: zero accumulators + twiddle tables ----------------
__global__ void init_kernel() {
    int i = blockIdx.x * blockDim.x + threadIdx.x;
    int stride = gridDim.x * blockDim.x;
    for (int j = i; j < B_*TOTL; j += stride) g_cmll[j] = 0LL;
    for (int j = i; j < NSEG*256; j += stride) g_hist[j] = 0u;
    if (i < NSEG) { g_sumll[i] = 0LL; g_sqll[i] = 0LL; g_pcount[i] = 0; }
    for (int j = i; j < 896; j += stride) {
        int N, jj;
        if (j < 512)      { N = 1024; jj = j; }
        else if (j < 768) { N = 512;  jj = j - 512; }
        else              { N = 256;  jj = j - 768; }
        double a = -6.283185307179586476925286766559 * (double)jj / (double)N;
        double sv, cv; sincos(a, &sv, &cv);
        g_twid[j] = make_float2((float)cv, (float)sv);
    }
}

// ---------------- transpose [B,L,CH] -> [B,CH,L] ----------------
__global__ void transpose3_kernel(const float* __restrict__ q,
                                  const float* __restrict__ k,
                                  const float* __restrict__ v) {
    __shared__ float tile[32][33];
    int b   = blockIdx.z;
    int ch0 = blockIdx.x * 32;
    int l0  = blockIdx.y * 32;
    const float* ins[3] = {q, k, v};
    float* outs[3] = {g_qT, g_kT, g_vT};
    int tx = threadIdx.x, ty = threadIdx.y;
    #pragma unroll
    for (int m = 0; m < 3; m++) {
        const float* in = ins[m];
        float* out = outs[m];
        for (int r = ty; r < 32; r += 8)
            tile[r][tx] = in[((size_t)b * L_ + (l0 + r)) * CH + ch0 + tx];
        __syncthreads();
        for (int r = ty; r < 32; r += 8)
            out[((size_t)b * CH + (ch0 + r)) * L_ + l0 + tx] = tile[tx][r];
        __syncthreads();
    }
}

// ---------------- radix-4 (merged radix-2 pairs) in-place DIT FFT ----------------
__device__ __forceinline__ void fft_pairs(float* sr, float* si, int N, int logN,
                                          const float2* __restrict__ tw, bool inv, int tid) {
    int st = 1;
    if (logN & 1) {                       // odd log2 -> one twiddle-free radix-2 stage
        for (int j = tid; j < (N >> 1); j += TPB) {
            int i0 = j << 1;
            float ur = sr[i0], ui = si[i0], vr = sr[i0+1], vi = si[i0+1];
            sr[i0] = ur + vr; si[i0] = ui + vi;
            sr[i0+1] = ur - vr; si[i0+1] = ui - vi;
        }
        __syncthreads();
        st = 2;
    }
    int groups = N >> 2;
    for (; st < logN; st += 2) {
        int half = 1 << (st - 1);
        for (int g = tid; g < groups; g += TPB) {
            int pos = g & (half - 1);
            int blk = g >> (st - 1);
            int i0 = (blk << (st + 1)) + pos;
            int i1 = i0 + half, i2 = i1 + half, i3 = i2 + half;
            float2 w = tw[pos << (logN - st - 1)];
            float wbr = w.x, wbi = inv ? -w.y : w.y;
            float war = wbr*wbr - wbi*wbi;
            float wai = 2.0f*wbr*wbi;
            float a0r = sr[i0], a0i = si[i0], a1r = sr[i1], a1i = si[i1];
            float a2r = sr[i2], a2i = si[i2], a3r = sr[i3], a3i = si[i3];
            float t1r = war*a1r - wai*a1i, t1i = war*a1i + wai*a1r;
            float b0r = a0r + t1r, b0i = a0i + t1i;
            float b1r = a0r - t1r, b1i = a0i - t1i;
            float t3r = war*a3r - wai*a3i, t3i = war*a3i + wai*a3r;
            float b2r = a2r + t3r, b2i = a2i + t3i;
            float b3r = a2r - t3r, b3i = a2i - t3i;
            float u2r = wbr*b2r - wbi*b2i, u2i = wbr*b2i + wbi*b2r;
            float u3r = wbr*b3r - wbi*b3i, u3i = wbr*b3i + wbi*b3r;
            float vr3, vi3;
            if (!inv) { vr3 =  u3i; vi3 = -u3r; }   // * (-i)
            else      { vr3 = -u3i; vi3 =  u3r; }   // * (+i)
            sr[i0] = b0r + u2r; si[i0] = b0i + u2i;
            sr[i2] = b0r - u2r; si[i2] = b0i - u2i;
            sr[i1] = b1r + vr3; si[i1] = b1i + vi3;
            sr[i3] = b1r - vr3; si[i3] = b1i - vi3;
        }
        __syncthreads();
    }
}

// ---------------- corr (all scales): packed FFT + fused stats/cm/peak-compaction ----------------
__global__ void corr_all_kernel() {
    extern __shared__ float smem[];
    __shared__ double rs[TPB];
    __shared__ double rq[TPB];
    __shared__ int s_cnt, s_base;
    int sIdx = blockIdx.x >> 13;
    int ch   = blockIdx.x & (NCH - 1);
    int b    = ch >> 9;
    int Ls = cLs[sIdx], logN = cLogN[sIdx];
    int seg = sIdx * 16 + b;
    float* sr = smem;
    float* si = smem + Ls;
    const float2* tw = g_twid + cTwOff[sIdx];
    int tid = threadIdx.x;
    int shv = 32 - logN;

    // load full-res rows, pool on the fly, bit-reverse scatter
    {
        float4 qa = ((const float4*)(g_qT + (size_t)ch * L_))[tid];
        float4 ka = ((const float4*)(g_kT + (size_t)ch * L_))[tid];
        if (sIdx == 0) {
            int t0 = tid * 4;
            sr[__brev((unsigned)(t0  )) >> shv] = qa.x; si[__brev((unsigned)(t0  )) >> shv] = ka.x;
            sr[__brev((unsigned)(t0+1)) >> shv] = qa.y; si[__brev((unsigned)(t0+1)) >> shv] = ka.y;
            sr[__brev((unsigned)(t0+2)) >> shv] = qa.z; si[__brev((unsigned)(t0+2)) >> shv] = ka.z;
            sr[__brev((unsigned)(t0+3)) >> shv] = qa.w; si[__brev((unsigned)(t0+3)) >> shv] = ka.w;
        } else if (sIdx == 1) {
            int t0 = tid * 2;
            sr[__brev((unsigned)(t0  )) >> shv] = (qa.x + qa.y) * 0.5f;
            si[__brev((unsigned)(t0  )) >> shv] = (ka.x + ka.y) * 0.5f;
            sr[__brev((unsigned)(t0+1)) >> shv] = (qa.z + qa.w) * 0.5f;
            si[__brev((unsigned)(t0+1)) >> shv] = (ka.z + ka.w) * 0.5f;
        } else {
            sr[__brev((unsigned)tid) >> shv] = (qa.x + qa.y + qa.z + qa.w) * 0.25f;
            si[__brev((unsigned)tid) >> shv] = (ka.x + ka.y + ka.z + ka.w) * 0.25f;
        }
    }
    __syncthreads();

    fft_pairs(sr, si, Ls, logN, tw, false, tid);

    // S[f] = Q[f]*conj(K[f]); mirror
    {
        float Srv[3], Siv[3]; int fv[3]; int nf = 0;
        for (int f = tid; f <= Ls / 2; f += TPB) {
            int g = (Ls - f) & (Ls - 1);
            float a = sr[f], bq = si[f];
            float c = sr[g], d  = si[g];
            float qr = 0.5f * (a + c),  qi = 0.5f * (bq - d);
            float kr = 0.5f * (bq + d), ki = 0.5f * (a - c);
            Srv[nf] = qr * kr - qi * ki;
            Siv[nf] = qr * ki + qi * kr;
            fv[nf]  = f; nf++;
        }
        __syncthreads();
        for (int ii = 0; ii < nf; ii++) {
            int f = fv[ii]; int g = (Ls - f) & (Ls - 1);
            sr[f] = Srv[ii]; si[f] =  Siv[ii];
            sr[g] = Srv[ii]; si[g] = -Siv[ii];
        }
        __syncthreads();
    }

    // bit-reverse permute for second DIT pass
    for (int t = tid; t < Ls; t += TPB) {
        int r = __brev((unsigned)t) >> shv;
        if (r > t) {
            float a = sr[t]; sr[t] = sr[r]; sr[r] = a;
            float bb = si[t]; si[t] = si[r]; si[r] = bb;
        }
    }
    __syncthreads();

    fft_pairs(sr, si, Ls, logN, tw, true, tid);

    // ---- fused epilogue: write corr, stats, cm atomics, peak compaction ----
    const float invN = 1.0f / (float)Ls;   // exact power of two
    float* outRow = g_corr + corrOff(sIdx) + (size_t)ch * Ls;
    double sm = 0.0, sq = 0.0;
    int nv = Ls >> 2;
    if (tid < nv) {
        int t0 = tid * 4;
        float v0 = sr[t0] * invN, v1 = sr[t0+1] * invN, v2 = sr[t0+2] * invN, v3 = sr[t0+3] * invN;
        ((float4*)outRow)[tid] = make_float4(v0, v1, v2, v3);
        sm = (double)v0 + (double)v1 + (double)v2 + (double)v3;
        sq = (double)v0*v0 + (double)v1*v1 + (double)v2*v2 + (double)v3*v3;
        long long* cmp = g_cmll + cCmSeg[sIdx] + b * Ls + t0;
        atomicAdd((unsigned long long*)(cmp  ), (unsigned long long)__float2ll_rn(v0 * SCCM));
        atomicAdd((unsigned long long*)(cmp+1), (unsigned long long)__float2ll_rn(v1 * SCCM));
        atomicAdd((unsigned long long*)(cmp+2), (unsigned long long)__float2ll_rn(v2 * SCCM));
        atomicAdd((unsigned long long*)(cmp+3), (unsigned long long)__float2ll_rn(v3 * SCCM));
    }
    rs[tid] = sm; rq[tid] = sq;
    if (tid == 0) s_cnt = 0;
    __syncthreads();
    for (int o = TPB / 2; o > 0; o >>= 1) {
        if (tid < o) { rs[tid] += rs[tid + o]; rq[tid] += rq[tid + o]; }
        __syncthreads();
    }
    if (tid == 0) {
        atomicAdd((unsigned long long*)&g_sumll[seg], (unsigned long long)__double2ll_rn(rs[0] * SCST));
        atomicAdd((unsigned long long*)&g_sqll[seg],  (unsigned long long)__double2ll_rn(rq[0] * SCST));
    }

    int loc = 0;
    for (int t = tid + 1; t < Ls - 1; t += TPB) {
        float v = sr[t];
        if (v > sr[t - 1] && v > sr[t + 1]) loc++;
    }
    if (loc) atomicAdd(&s_cnt, loc);
    __syncthreads();
    if (tid == 0) { s_base = atomicAdd(&g_pcount[seg], s_cnt); s_cnt = 0; }
    __syncthreads();
    unsigned* keys = g_pkeys + corrOff(sIdx) + (size_t)b * CH * Ls;
    for (int t = tid + 1; t < Ls - 1; t += TPB) {
        float v = sr[t];
        if (v > sr[t - 1] && v > sr[t + 1]) {
            int pos = atomicAdd(&s_cnt, 1);
            keys[s_base + pos] = f2k(v * invN);
        }
    }
}

// ---------------- pk feature + tiny MLP per (scale,batch) segment ----------------
__global__ void pkmlp_kernel(const float* __restrict__ w1, const float* __restrict__ b1,
                             const float* __restrict__ w2, const float* __restrict__ b2,
                             const float* __restrict__ w3, const float* __restrict__ b3) {
    __shared__ int red[TPB];
    int seg = blockIdx.x;
    int sIdx = seg >> 4, b = seg & 15;
    int Ls = cLs[sIdx];
    int tid = threadIdx.x;
    const long long* cm = g_cmll + cCmSeg[sIdx] + b * Ls;
    int cnt = 0;
    for (int t = tid + 1; t < Ls - 1; t += TPB) {
        long long v = cm[t];
        if (v > cm[t - 1] && v > cm[t + 1]) cnt++;
    }
    red[tid] = cnt;
    __syncthreads();
    for (int o = TPB / 2; o > 0; o >>= 1) {
        if (tid < o) red[tid] += red[tid + o];
        __syncthreads();
    }
    if (tid == 0) {
        const double invSC = 1.0 / SCST;
        float f2 = (float)red[0];
        long long tot = 0;
        for (int i = 0; i < B_; i++) tot += g_sqll[sIdx * 16 + i];
        float f0 = (float)((double)tot * invSC / ((double)B_ * (double)Ls));
        double n = (double)CH * (double)Ls;
        double s1 = (double)g_sumll[seg] * invSC;
        double s2 = (double)g_sqll[seg] * invSC;
        double mean = s1 / n;
        float f1 = (float)((s2 - mean * s1) / (n - 1.0));
        float h1[32];
        for (int j = 0; j < 32; j++) {
            float a = w1[j*3] * f0 + w1[j*3+1] * f1 + w1[j*3+2] * f2 + b1[j];
            h1[j] = a > 0.0f ? a : 0.0f;
        }
        float h2[16];
        for (int j = 0; j < 16; j++) {
            float a = b2[j];
            for (int i2 = 0; i2 < 32; i2++) a += w2[j*32+i2] * h1[i2];
            h2[j] = a > 0.0f ? a : 0.0f;
        }
        float a = b3[0];
        for (int i2 = 0; i2 < 16; i2++) a += w3[i2] * h2[i2];
        float ratio = 1.0f / (1.0f + expf(-a));
        int kv = (int)(ratio * (float)Ls);
        if (kv < 1) kv = 1;
        if (kv > Ls) kv = Ls;
        g_kvals[seg] = kv;
        g_krem[seg]  = kv;
        g_prefix[seg] = 0u;
    }
}

// ---------------- radix select (all 48 segments per pass) ----------------
__global__ void hist_kernel(int sh, int first) {
    __shared__ unsigned hl[256];
    int seg = blockIdx.y;
    int sIdx = seg >> 4, b = seg & 15;
    for (int i = threadIdx.x; i < 256; i += blockDim.x) hl[i] = 0;
    __syncthreads();
    int cnt = g_pcount[seg];
    unsigned ph = first ? 0u : (g_prefix[seg] >> (sh + 8));
    const unsigned* keys = g_pkeys + corrOff(sIdx) + (size_t)b * CH * cLs[sIdx];
    for (int i = blockIdx.x * blockDim.x + threadIdx.x; i < cnt; i += gridDim.x * blockDim.x) {
        unsigned key = keys[i];
        if (first || (key >> (sh + 8)) == ph)
            atomicAdd(&hl[(key >> sh) & 255u], 1u);
    }
    __syncthreads();
    for (int i = threadIdx.x; i < 256; i += blockDim.x)
        if (hl[i]) atomicAdd(&g_hist[seg * 256 + i], hl[i]);
}

__global__ void scan_kernel(int sh, int last) {
    int tid = threadIdx.x;
    if (tid < NSEG) {
        int seg = tid;
        unsigned k = (unsigned)g_krem[seg];
        unsigned cum = 0; unsigned chosen = 0;
        for (int bin = 255; bin >= 0; --bin) {
            unsigned h = g_hist[seg * 256 + bin];
            if (cum + h >= k) { chosen = (unsigned)bin; g_krem[seg] = (int)(k - cum); break; }
            cum += h;
        }
        g_prefix[seg] |= chosen << sh;
        if (last) g_thresh[seg] = k2f(g_prefix[seg]);
    }
    __syncthreads();
    for (int i = tid; i < NSEG * 256; i += blockDim.x) g_hist[i] = 0u;
}

// ---------------- final: masked softmax * pooled v + interpolation (all scales) ----------------
__global__ void final_all_kernel(const float* __restrict__ swarr) {
    extern __shared__ float smem[];
    __shared__ float red[TPB];
    int sIdx = blockIdx.x >> 13;
    int ch   = blockIdx.x & (NCH - 1);
    int b    = ch >> 9;
    int seg  = sIdx * 16 + b;
    int Ls = cLs[sIdx];
    int s  = 1 << sIdx;
    int tid = threadIdx.x;
    float* sc = smem;
    float* so = smem + Ls;

    const float4* c4 = (const float4*)(g_corr + corrOff(sIdx) + (size_t)ch * Ls);
    int nv = Ls >> 2;
    if (tid < nv) ((float4*)sc)[tid] = c4[tid];
    __syncthreads();

    float thr = g_thresh[seg];
    bool useAll = (g_pcount[seg] <= g_kvals[seg]);

    float m = 0.0f;
    for (int t = tid; t < Ls; t += TPB) {
        float a = 0.0f;
        if (t > 0 && t < Ls - 1) {
            float v = sc[t];
            if (v > sc[t - 1] && v > sc[t + 1] && (useAll || v >= thr)) a = v;
        }
        so[t] = a;
        m = fmaxf(m, a);
    }
    red[tid] = m; __syncthreads();
    for (int o = TPB / 2; o > 0; o >>= 1) {
        if (tid < o) red[tid] = fmaxf(red[tid], red[tid + o]);
        __syncthreads();
    }
    m = red[0]; __syncthreads();

    float ds = 0.0f;
    for (int t = tid; t < Ls; t += TPB) ds += __expf(so[t] - m);
    red[tid] = ds; __syncthreads();
    for (int o = TPB / 2; o > 0; o >>= 1) {
        if (tid < o) red[tid] += red[tid + o];
        __syncthreads();
    }
    float inv = 1.0f / red[0];
    __syncthreads();

    // so[t] = weight(t) * pooled_v(t)
    {
        float4 vv = ((const float4*)(g_vT + (size_t)ch * L_))[tid];
        if (sIdx == 0) {
            int t0 = tid * 4;
            so[t0  ] = __expf(so[t0  ] - m) * inv * vv.x;
            so[t0+1] = __expf(so[t0+1] - m) * inv * vv.y;
            so[t0+2] = __expf(so[t0+2] - m) * inv * vv.z;
            so[t0+3] = __expf(so[t0+3] - m) * inv * vv.w;
        } else if (sIdx == 1) {
            int t0 = tid * 2;
            so[t0  ] = __expf(so[t0  ] - m) * inv * ((vv.x + vv.y) * 0.5f);
            so[t0+1] = __expf(so[t0+1] - m) * inv * ((vv.z + vv.w) * 0.5f);
        } else {
            so[tid] = __expf(so[tid] - m) * inv * ((vv.x + vv.y + vv.z + vv.w) * 0.25f);
        }
    }
    __syncthreads();

    float sw = swarr[sIdx];
    float* outRow = g_out3 + (size_t)sIdx * NCH * L_ + (size_t)ch * L_;
    if (s == 1) {
        float4 o4 = make_float4(sw * so[tid*4], sw * so[tid*4+1], sw * so[tid*4+2], sw * so[tid*4+3]);
        ((float4*)outRow)[tid] = o4;
    } else {
        float invs = 1.0f / (float)s;
        for (int t = tid; t < L_; t += TPB) {
            float src = ((float)t + 0.5f) * invs - 0.5f;
            if (src < 0.0f) src = 0.0f;
            int x0 = (int)src;
            int x1 = x0 + 1; if (x1 > Ls - 1) x1 = Ls - 1;
            float lam = src - (float)x0;
            outRow[t] = sw * (so[x0] * (1.0f - lam) + so[x1] * lam);
        }
    }
}

// ---------------- untranspose + sum 3 scales: [B,CH,L] -> [B,L,CH] ----------------
__global__ void untranspose_kernel(float* __restrict__ out) {
    __shared__ float tile[32][33];
    int b   = blockIdx.z;
    int ch0 = blockIdx.x * 32;
    int l0  = blockIdx.y * 32;
    int tx = threadIdx.x, ty = threadIdx.y;
    const float* o0 = g_out3;
    const float* o1 = g_out3 + (size_t)NCH * L_;
    const float* o2 = g_out3 + (size_t)2 * NCH * L_;
    for (int r = ty; r < 32; r += 8) {
        size_t idx = ((size_t)b * CH + (ch0 + r)) * L_ + l0 + tx;
        tile[r][tx] = o0[idx] + o1[idx] + o2[idx];
    }
    __syncthreads();
    for (int r = ty; r < 32; r += 8)
        out[((size_t)b * L_ + (l0 + r)) * CH + ch0 + tx] = tile[tx][r];
}

// ---------------- launch ----------------
extern "C" void kernel_launch(void* const* d_in, const int* in_sizes, int n_in,
                              void* d_out, int out_size) {
    (void)in_sizes; (void)n_in; (void)out_size;
    const float* q  = (const float*)d_in[0];
    const float* kk = (const float*)d_in[1];
    const float* v  = (const float*)d_in[2];
    const float* sw = (const float*)d_in[3];
    const float* w1 = (const float*)d_in[4];
    const float* b1 = (const float*)d_in[5];
    const float* w2 = (const float*)d_in[6];
    const float* b2 = (const float*)d_in[7];
    const float* w3 = (const float*)d_in[8];
    const float* b3 = (const float*)d_in[9];
    float* out = (float*)d_out;

    init_kernel<<<64, TPB>>>();

    dim3 tgrid(CH / 32, L_ / 32, B_);
    dim3 tblk(32, 8);
    transpose3_kernel<<<tgrid, tblk>>>(q, kk, v);

    corr_all_kernel<<<3 * NCH, TPB, 2 * 1024 * sizeof(float)>>>();
    pkmlp_kernel<<<NSEG, TPB>>>(w1, b1, w2, b2, w3, b3);

    for (int p = 0; p < 4; p++) {
        dim3 hg(32, NSEG);
        hist_kernel<<<hg, TPB>>>(24 - 8 * p, p == 0 ? 1 : 0);
        scan_kernel<<<1, TPB>>>(24 - 8 * p, p == 3 ? 1 : 0);
    }

    final_all_kernel<<<3 * NCH, TPB, 2 * 1024 * sizeof(float)>>>(sw);

    untranspose_kernel<<<tgrid, tblk>>>(out);
}